// round 13
// baseline (speedup 1.0000x reference)
#include <cuda_runtime.h>
#include <cuda_fp16.h>
#include <stdint.h>
#include <math.h>

#define Bsz 4
#define Tsz 2048
#define Dsz 1024
#define BT  (Bsz * Tsz)

typedef __half h16;

// ---------------- scratch (__device__ globals; allocation-free rule) -------
__device__ __align__(16) h16 g_xf[(size_t)BT * Dsz];
__device__ __align__(16) h16 g_wqt[(size_t)Dsz * Dsz];       // Wq^T fp16
__device__ __align__(16) h16 g_wk[(size_t)Dsz * Dsz];        // Wk fp16
__device__ __align__(16) h16 g_mp[4][(size_t)Dsz * Dsz];     // M split-K partials
__device__ __align__(16) h16 g_bc[(size_t)Dsz * 2 * Dsz];    // B' = [M | Wv^T]
__device__ __align__(16) h16 g_av[(size_t)BT * 2 * Dsz];     // [A | V]
__device__ __align__(16) h16 g_pf[(size_t)Bsz * Tsz * Tsz];  // P (unnormalized)
__device__ __align__(16) float g_rsum[(size_t)Bsz * Tsz];    // softmax row sums

// ---------------- low-level helpers (plain sm_80-era PTX only) --------------
__device__ __forceinline__ uint32_t smem_u32(const void* p) {
    uint32_t a;
    asm("{ .reg .u64 t; cvta.to.shared.u64 t, %1; cvt.u32.u64 %0, t; }"
        : "=r"(a) : "l"(p));
    return a;
}

#define CP_ASYNC16(dst, src) \
    asm volatile("cp.async.cg.shared.global [%0], [%1], 16;" \
                 :: "r"(dst), "l"(src))
#define CP_COMMIT() asm volatile("cp.async.commit_group;")
#define CP_WAIT1()  asm volatile("cp.async.wait_group 1;")

__device__ __forceinline__ void ldsm4(uint32_t& r0, uint32_t& r1,
                                      uint32_t& r2, uint32_t& r3,
                                      uint32_t addr) {
    asm volatile("ldmatrix.sync.aligned.m8n8.x4.shared.b16 {%0,%1,%2,%3}, [%4];"
                 : "=r"(r0), "=r"(r1), "=r"(r2), "=r"(r3) : "r"(addr));
}

__device__ __forceinline__ void ldsm4t(uint32_t& r0, uint32_t& r1,
                                       uint32_t& r2, uint32_t& r3,
                                       uint32_t addr) {
    asm volatile(
        "ldmatrix.sync.aligned.m8n8.x4.trans.shared.b16 {%0,%1,%2,%3}, [%4];"
        : "=r"(r0), "=r"(r1), "=r"(r2), "=r"(r3) : "r"(addr));
}

__device__ __forceinline__ void mma16816(float* d, const uint32_t* a,
                                         const uint32_t* b) {
    asm volatile(
        "mma.sync.aligned.m16n8k16.row.col.f32.f16.f16.f32 "
        "{%0,%1,%2,%3}, {%4,%5,%6,%7}, {%8,%9}, {%0,%1,%2,%3};"
        : "+f"(d[0]), "+f"(d[1]), "+f"(d[2]), "+f"(d[3])
        : "r"(a[0]), "r"(a[1]), "r"(a[2]), "r"(a[3]), "r"(b[0]), "r"(b[1]));
}

// ---------------- HMMA GEMM (proven at-ceiling config) -----------------------
// C[M,N] = A[M,K] * op(B).  bnn=0: B is [N,K] (NT).  bnn=1: B is [K,N] (NN).
// mode 0: full grid.  mode 1: triangular tile index.  mode 2: kend=row0+128.
// ofp16: fp16 C.  oexp: exp epilogue (fp16 P + atomic row sums, causal mask).
// oscale: fp32 C scaled by 1/rsum[row].
#define KC     64
#define ROWB   144
#define ROWBB  272
#define MATB   (128 * ROWB)
#define STGB   (2 * MATB)
#define NSTG   3
#define SMEMB  (NSTG * STGB)     // 110592 B
#define SMSCALE 0.03125f         // 1/sqrt(1024)

__global__ void __launch_bounds__(256, 2) hgemm(
    const h16* __restrict__ Af, const h16* __restrict__ Bf,
    void* __restrict__ Cv, float* __restrict__ rsum,
    int K, int lda, int ldb, int ldc,
    int mode, int ofp16, int bnn, int oexp, int oscale,
    long long sA, long long sB, long long sC)
{
    const int bz = blockIdx.z;
    Af += (size_t)bz * sA;
    Bf += (size_t)bz * sB;

    int row0, col0;
    if (mode == 1) {
        const int t = blockIdx.x;
        int r = (int)((__fsqrt_rn(8.f * (float)t + 1.f) - 1.f) * 0.5f);
        while ((r + 1) * (r + 2) / 2 <= t) r++;
        while (r * (r + 1) / 2 > t) r--;
        row0 = r * 128;
        col0 = (t - r * (r + 1) / 2) * 128;
    } else if (mode == 2) {
        const int by = (int)gridDim.y - 1 - (int)blockIdx.y;  // heavy first
        row0 = by * 128;
        col0 = blockIdx.x * 128;
    } else {
        row0 = blockIdx.y * 128;
        col0 = blockIdx.x * 128;
    }
    const int kend = (mode == 2) ? (row0 + 128) : K;
    const int nc = kend / KC;

    extern __shared__ char smc[];
    const uint32_t smb = smem_u32(smc);
    const int tid  = threadIdx.x;
    const int lane = tid & 31;
    const int wid  = tid >> 5;
    const int m0 = (wid & 1) * 64;
    const int n0 = (wid >> 1) * 32;

    float acc[4][4][4];
#pragma unroll
    for (int i = 0; i < 4; i++)
#pragma unroll
        for (int j = 0; j < 4; j++)
#pragma unroll
            for (int q = 0; q < 4; q++) acc[i][j][q] = 0.f;

    const int lch  = tid & 7;
    const int lr0  = tid >> 3;
    const int lch2 = tid & 15;
    const int lr2  = tid >> 4;

    auto do_load = [&](int st, int k0) {
        const uint32_t sb = smb + (uint32_t)st * STGB;
        const h16* pA = Af + (size_t)row0 * lda + k0;
#pragma unroll
        for (int j = 0; j < 4; j++) {
            const int row = lr0 + j * 32;
            CP_ASYNC16(sb + (uint32_t)(row * ROWB + lch * 16),
                       pA + (size_t)row * lda + lch * 8);
        }
        if (!bnn) {
            const h16* pB = Bf + (size_t)col0 * ldb + k0;
#pragma unroll
            for (int j = 0; j < 4; j++) {
                const int row = lr0 + j * 32;
                CP_ASYNC16(sb + MATB + (uint32_t)(row * ROWB + lch * 16),
                           pB + (size_t)row * ldb + lch * 8);
            }
        } else {
            const h16* pB = Bf + (size_t)k0 * ldb + col0;
#pragma unroll
            for (int j = 0; j < 4; j++) {
                const int row = lr2 + j * 16;
                CP_ASYNC16(sb + MATB + (uint32_t)(row * ROWBB + lch2 * 16),
                           pB + (size_t)row * ldb + lch2 * 8);
            }
        }
    };

    do_load(0, 0);
    CP_COMMIT();
    do_load(1, KC);
    CP_COMMIT();

    for (int c = 0; c < nc; c++) {
        CP_WAIT1();
        __syncthreads();
        if (c + 2 < nc) do_load((c + 2) % NSTG, (c + 2) * KC);
        CP_COMMIT();

        const uint32_t base = smb + (uint32_t)(c % NSTG) * STGB;
#pragma unroll
        for (int kk = 0; kk < 4; kk++) {
            uint32_t a[4][4];
#pragma unroll
            for (int mi = 0; mi < 4; mi++) {
                const uint32_t ad = base +
                    (uint32_t)((m0 + mi * 16 + (lane & 15)) * ROWB +
                               (kk * 2 + (lane >> 4)) * 16);
                ldsm4(a[mi][0], a[mi][1], a[mi][2], a[mi][3], ad);
            }
            uint32_t bb[4][2];
            if (!bnn) {
#pragma unroll
                for (int np = 0; np < 2; np++) {
                    const int rb = n0 + np * 16 + (lane & 7) + ((lane >> 4) << 3);
                    const int ch = kk * 2 + ((lane >> 3) & 1);
                    const uint32_t ad = base + MATB +
                        (uint32_t)(rb * ROWB + ch * 16);
                    ldsm4(bb[np*2][0], bb[np*2][1],
                          bb[np*2+1][0], bb[np*2+1][1], ad);
                }
            } else {
#pragma unroll
                for (int g = 0; g < 2; g++) {
                    const uint32_t ad = base + MATB +
                        (uint32_t)((kk * 16 + (lane & 15)) * ROWBB +
                                   (n0 + g * 16 + ((lane >> 4) << 3)) * 2);
                    ldsm4t(bb[g*2][0], bb[g*2][1],
                           bb[g*2+1][0], bb[g*2+1][1], ad);
                }
            }
#pragma unroll
            for (int mi = 0; mi < 4; mi++)
#pragma unroll
                for (int ni = 0; ni < 4; ni++)
                    mma16816(acc[mi][ni], a[mi], bb[ni]);
        }
    }

    // ---------------- epilogues ----------------
    const int er = lane >> 2;
    const int ec = (lane & 3) * 2;

    if (oexp) {
        h16* C = (h16*)Cv + (size_t)bz * sC;
        float* rs = rsum + (size_t)bz * Tsz;
#pragma unroll
        for (int mi = 0; mi < 4; mi++) {
            const int rlo = row0 + m0 + mi * 16 + er;
            const int rhi = rlo + 8;
            float slo = 0.f, shi = 0.f;
#pragma unroll
            for (int ni = 0; ni < 4; ni++) {
                const int cc = col0 + n0 + ni * 8 + ec;
                float p0 = (cc     <= rlo) ? __expf(acc[mi][ni][0] * SMSCALE) : 0.f;
                float p1 = (cc + 1 <= rlo) ? __expf(acc[mi][ni][1] * SMSCALE) : 0.f;
                float p2 = (cc     <= rhi) ? __expf(acc[mi][ni][2] * SMSCALE) : 0.f;
                float p3 = (cc + 1 <= rhi) ? __expf(acc[mi][ni][3] * SMSCALE) : 0.f;
                __half2 h0 = __floats2half2_rn(p0, p1);
                __half2 h1 = __floats2half2_rn(p2, p3);
                *(__half2*)&C[(size_t)rlo * ldc + cc] = h0;
                *(__half2*)&C[(size_t)rhi * ldc + cc] = h1;
                slo += p0 + p1;
                shi += p2 + p3;
            }
            slo += __shfl_xor_sync(0xffffffffu, slo, 1);
            slo += __shfl_xor_sync(0xffffffffu, slo, 2);
            shi += __shfl_xor_sync(0xffffffffu, shi, 1);
            shi += __shfl_xor_sync(0xffffffffu, shi, 2);
            if ((lane & 3) == 0) {
                atomicAdd(&rs[rlo], slo);
                atomicAdd(&rs[rhi], shi);
            }
        }
    } else if (!ofp16) {
        float* C = (float*)Cv + (size_t)bz * sC;
        const float* rs = rsum + (size_t)bz * Tsz;
#pragma unroll
        for (int mi = 0; mi < 4; mi++) {
            const int r = row0 + m0 + mi * 16 + er;
            float ilo = 1.f, ihi = 1.f;
            if (oscale) {
                ilo = __fdividef(1.f, rs[r]);
                ihi = __fdividef(1.f, rs[r + 8]);
            }
#pragma unroll
            for (int ni = 0; ni < 4; ni++) {
                const int cc = col0 + n0 + ni * 8 + ec;
                *(float2*)&C[(size_t)r * ldc + cc] =
                    make_float2(acc[mi][ni][0] * ilo, acc[mi][ni][1] * ilo);
                *(float2*)&C[(size_t)(r + 8) * ldc + cc] =
                    make_float2(acc[mi][ni][2] * ihi, acc[mi][ni][3] * ihi);
            }
        }
    } else {
        h16* C = (h16*)Cv + (size_t)bz * sC;
#pragma unroll
        for (int mi = 0; mi < 4; mi++) {
            const int r = row0 + m0 + mi * 16 + er;
#pragma unroll
            for (int ni = 0; ni < 4; ni++) {
                const int cc = col0 + n0 + ni * 8 + ec;
                __half2 h0 = __floats2half2_rn(acc[mi][ni][0], acc[mi][ni][1]);
                __half2 h1 = __floats2half2_rn(acc[mi][ni][2], acc[mi][ni][3]);
                *(__half2*)&C[(size_t)r * ldc + cc] = h0;
                *(__half2*)&C[(size_t)(r + 8) * ldc + cc] = h1;
            }
        }
    }
}

// ---------------- prep kernels (weights / x split for stream overlap) -------
#define NXB (BT * Dsz / 1024)        // 8192 blocks for x
#define NWB (Dsz * Dsz / 1024)       // 1024 blocks per weight

__global__ void __launch_bounds__(256) prep_x(
    const float* __restrict__ x, h16* __restrict__ xf)
{
    const int i = blockIdx.x * 256 + threadIdx.x;
    float4 v = ((const float4*)x)[i];
    __half2 p0 = __floats2half2_rn(v.x, v.y);
    __half2 p1 = __floats2half2_rn(v.z, v.w);
    uint2 u;
    u.x = *(uint32_t*)&p0;
    u.y = *(uint32_t*)&p1;
    ((uint2*)xf)[i] = u;
}

__global__ void __launch_bounds__(256) prep_w(
    const float* __restrict__ Wq, const float* __restrict__ Wk,
    const float* __restrict__ Wv,
    h16* __restrict__ wqt, h16* __restrict__ wkf,
    h16* __restrict__ wvt /* ld 2*Dsz */)
{
    __shared__ float tile[32][33];
    const int bid = blockIdx.x;
    const int tid = threadIdx.x;

    if (bid < NWB) {
        // straight fp16 convert of Wk
        const int i = bid * 256 + tid;
        float4 v = ((const float4*)Wk)[i];
        __half2 p0 = __floats2half2_rn(v.x, v.y);
        __half2 p1 = __floats2half2_rn(v.z, v.w);
        uint2 u;
        u.x = *(uint32_t*)&p0;
        u.y = *(uint32_t*)&p1;
        ((uint2*)wkf)[i] = u;
    } else {
        const int t = bid - NWB;
        const bool isq = t < NWB;
        const int tt = isq ? t : t - NWB;
        const float* w = isq ? Wq : Wv;
        h16* o = isq ? wqt : wvt;
        const int ldo = isq ? Dsz : 2 * Dsz;
        const int d0 = (tt & 31) * 32;
        const int o0 = (tt >> 5) * 32;
        const int tx = tid & 31, ty = tid >> 5;
#pragma unroll
        for (int j = ty; j < 32; j += 8)
            tile[j][tx] = w[(size_t)(o0 + j) * Dsz + d0 + tx];
        __syncthreads();
#pragma unroll
        for (int j = ty; j < 32; j += 8)
            o[(size_t)(d0 + j) * ldo + o0 + tx] = __float2half_rn(tile[tx][j]);
    }
}

// ---------------- conv_m: sum 4 fp16 split-K partials -> B' cols [0,1024) ---
__global__ void __launch_bounds__(256) conv_m(
    const h16* __restrict__ mp, h16* __restrict__ bc)
{
    const int i = blockIdx.x * 256 + threadIdx.x;   // uint4 units
    const int row = i >> 7;
    const int cb  = i & 127;
    const uint4* p = (const uint4*)mp;
    const int ps = (Dsz * Dsz) / 8;

    float2 f[4] = {{0,0},{0,0},{0,0},{0,0}};
#pragma unroll
    for (int k = 0; k < 4; k++) {
        uint4 u = p[(size_t)k * ps + i];
        const __half2* h = (const __half2*)&u;
#pragma unroll
        for (int j = 0; j < 4; j++) {
            float2 v = __half22float2(h[j]);
            f[j].x += v.x;
            f[j].y += v.y;
        }
    }
    uint4 o;
    __half2* oh = (__half2*)&o;
#pragma unroll
    for (int j = 0; j < 4; j++)
        oh[j] = __floats2half2_rn(f[j].x, f[j].y);
    ((uint4*)bc)[(size_t)row * 256 + cb] = o;
}

// ---------------- launch ------------------------------------------------------
extern "C" void kernel_launch(void* const* d_in, const int* in_sizes, int n_in,
                              void* d_out, int out_size)
{
    (void)in_sizes; (void)n_in; (void)out_size;
    const float* x  = (const float*)d_in[0];
    const float* Wq = (const float*)d_in[1];
    const float* Wk = (const float*)d_in[2];
    const float* Wv = (const float*)d_in[3];
    float* out = (float*)d_out;

    h16 *xf, *wqt, *wk, *mp, *bc, *av, *pf;
    float* rsum;
    cudaGetSymbolAddress((void**)&xf,   g_xf);
    cudaGetSymbolAddress((void**)&wqt,  g_wqt);
    cudaGetSymbolAddress((void**)&wk,   g_wk);
    cudaGetSymbolAddress((void**)&mp,   g_mp);
    cudaGetSymbolAddress((void**)&bc,   g_bc);
    cudaGetSymbolAddress((void**)&av,   g_av);
    cudaGetSymbolAddress((void**)&pf,   g_pf);
    cudaGetSymbolAddress((void**)&rsum, g_rsum);

    cudaFuncSetAttribute(hgemm, cudaFuncAttributeMaxDynamicSharedMemorySize,
                         SMEMB);

    // lazily created side stream + events (host objects only; created on the
    // eager correctness call, reused during graph capture)
    static cudaStream_t s2 = nullptr;
    static cudaEvent_t e0 = nullptr, e_x = nullptr, e_m = nullptr,
                       e_v = nullptr;
    if (!s2) {
        cudaStreamCreateWithFlags(&s2, cudaStreamNonBlocking);
        cudaEventCreateWithFlags(&e0,  cudaEventDisableTiming);
        cudaEventCreateWithFlags(&e_x, cudaEventDisableTiming);
        cudaEventCreateWithFlags(&e_m, cudaEventDisableTiming);
        cudaEventCreateWithFlags(&e_v, cudaEventDisableTiming);
    }

    // fork: s2 branches off the capture-origin (default) stream
    cudaEventRecord(e0, 0);
    cudaStreamWaitEvent(s2, e0, 0);

    // s2: zero rsum, convert x
    cudaMemsetAsync(rsum, 0, (size_t)Bsz * Tsz * sizeof(float), s2);
    prep_x<<<NXB, 256, 0, s2>>>(x, xf);
    cudaEventRecord(e_x, s2);

    // stream 0: weight prep -> M (split-K=4) -> reduce into B' cols [0,1024)
    prep_w<<<3 * NWB, 256>>>(Wq, Wk, Wv, wqt, wk, bc + Dsz);
    hgemm<<<dim3(Dsz / 128, Dsz / 128, 4), 256, SMEMB>>>(
        wqt, wk, mp, rsum, 256, Dsz, Dsz, Dsz, 0, 1, 1, 0, 0,
        256, (long long)256 * Dsz, (long long)Dsz * Dsz);
    conv_m<<<(Dsz * Dsz / 8) / 256, 256>>>(mp, bc);
    cudaEventRecord(e_m, 0);

    // stream 0: A = x @ M (needs xf + bc)
    cudaStreamWaitEvent(0, e_x, 0);
    hgemm<<<dim3(Dsz / 128, BT / 128, 1), 256, SMEMB>>>(
        xf, bc, av, rsum, Dsz, Dsz, 2 * Dsz, 2 * Dsz, 0, 1, 1, 0, 0, 0, 0, 0);

    // s2: V = x @ Wv^T (needs xf [s2-ordered] + bc via e_m) — overlaps A and S
    cudaStreamWaitEvent(s2, e_m, 0);
    hgemm<<<dim3(Dsz / 128, BT / 128, 1), 256, SMEMB, s2>>>(
        xf, bc + Dsz, av + Dsz, rsum, Dsz, Dsz, 2 * Dsz, 2 * Dsz,
        0, 1, 1, 0, 0, 0, 0, 0);
    cudaEventRecord(e_v, s2);

    const h16* am = av;             // A, row stride 2048
    const h16* vp = av + Dsz;       // V, row stride 2048

    // stream 0: P_unnorm = exp(scale * A @ x^T) (triangular, fused exp+rowsum)
    const int ntiles = (Tsz / 128) * (Tsz / 128 + 1) / 2;   // 136
    hgemm<<<dim3(ntiles, 1, Bsz), 256, SMEMB>>>(
        am, xf, pf, rsum, Dsz, 2 * Dsz, Dsz, Tsz, 1, 0, 0, 1, 0,
        (long long)Tsz * 2 * Dsz, (long long)Tsz * Dsz,
        (long long)Tsz * Tsz);

    // join: PV needs V; then O = (P @ V) * (1/rowsum)
    cudaStreamWaitEvent(0, e_v, 0);
    hgemm<<<dim3(Dsz / 128, Tsz / 128, Bsz), 256, SMEMB>>>(
        pf, vp, out, rsum, Tsz, Tsz, 2 * Dsz, Dsz, 2, 0, 1, 0, 1,
        (long long)Tsz * Tsz, (long long)Tsz * 2 * Dsz,
        (long long)Tsz * Dsz);
}

// round 14
// speedup vs baseline: 1.0275x; 1.0275x over previous
#include <cuda_runtime.h>
#include <cuda_fp16.h>
#include <stdint.h>
#include <math.h>

#define Bsz 4
#define Tsz 2048
#define Dsz 1024
#define BT  (Bsz * Tsz)

typedef __half h16;

// ---------------- scratch (__device__ globals; allocation-free rule) -------
__device__ __align__(16) h16 g_xf[(size_t)BT * Dsz];
__device__ __align__(16) h16 g_wqt[(size_t)Dsz * Dsz];       // Wq^T fp16
__device__ __align__(16) h16 g_wk[(size_t)Dsz * Dsz];        // Wk fp16
__device__ __align__(16) h16 g_mp[4][(size_t)Dsz * Dsz];     // M split-K partials
__device__ __align__(16) h16 g_bc[(size_t)Dsz * 2 * Dsz];    // B' = [M | Wv^T]
__device__ __align__(16) h16 g_av[(size_t)BT * 2 * Dsz];     // [A | V]
__device__ __align__(16) h16 g_pf[(size_t)Bsz * Tsz * Tsz];  // P (unnormalized)
__device__ __align__(16) float g_rsum[(size_t)Bsz * Tsz];    // softmax row sums

// ---------------- low-level helpers (plain sm_80-era PTX only) --------------
__device__ __forceinline__ uint32_t smem_u32(const void* p) {
    uint32_t a;
    asm("{ .reg .u64 t; cvta.to.shared.u64 t, %1; cvt.u32.u64 %0, t; }"
        : "=r"(a) : "l"(p));
    return a;
}

#define CP_ASYNC16(dst, src) \
    asm volatile("cp.async.cg.shared.global [%0], [%1], 16;" \
                 :: "r"(dst), "l"(src))
#define CP_COMMIT() asm volatile("cp.async.commit_group;")
#define CP_WAIT1()  asm volatile("cp.async.wait_group 1;")

__device__ __forceinline__ void ldsm4(uint32_t& r0, uint32_t& r1,
                                      uint32_t& r2, uint32_t& r3,
                                      uint32_t addr) {
    asm volatile("ldmatrix.sync.aligned.m8n8.x4.shared.b16 {%0,%1,%2,%3}, [%4];"
                 : "=r"(r0), "=r"(r1), "=r"(r2), "=r"(r3) : "r"(addr));
}

__device__ __forceinline__ void ldsm4t(uint32_t& r0, uint32_t& r1,
                                       uint32_t& r2, uint32_t& r3,
                                       uint32_t addr) {
    asm volatile(
        "ldmatrix.sync.aligned.m8n8.x4.trans.shared.b16 {%0,%1,%2,%3}, [%4];"
        : "=r"(r0), "=r"(r1), "=r"(r2), "=r"(r3) : "r"(addr));
}

__device__ __forceinline__ void mma16816(float* d, const uint32_t* a,
                                         const uint32_t* b) {
    asm volatile(
        "mma.sync.aligned.m16n8k16.row.col.f32.f16.f16.f32 "
        "{%0,%1,%2,%3}, {%4,%5,%6,%7}, {%8,%9}, {%0,%1,%2,%3};"
        : "+f"(d[0]), "+f"(d[1]), "+f"(d[2]), "+f"(d[3])
        : "r"(a[0]), "r"(a[1]), "r"(a[2]), "r"(a[3]), "r"(b[0]), "r"(b[1]));
}

// PDL: wait for the predecessor kernel's memory to be visible.
__device__ __forceinline__ void grid_dep_sync() {
    asm volatile("griddepcontrol.wait;" ::: "memory");
}

// ---------------- HMMA GEMM (proven at-ceiling config) -----------------------
// C[M,N] = A[M,K] * op(B).  bnn=0: B is [N,K] (NT).  bnn=1: B is [K,N] (NN).
// mode 0: full grid.  mode 1: triangular tile index.  mode 2: kend=row0+128.
// ofp16: fp16 C.  oexp: exp epilogue (fp16 P + atomic row sums, causal mask).
// oscale: fp32 C scaled by 1/rsum[row].
#define KC     64
#define ROWB   144
#define ROWBB  272
#define MATB   (128 * ROWB)
#define STGB   (2 * MATB)
#define NSTG   3
#define SMEMB  (NSTG * STGB)     // 110592 B
#define SMSCALE 0.03125f         // 1/sqrt(1024)

__global__ void __launch_bounds__(256, 2) hgemm(
    const h16* __restrict__ Af, const h16* __restrict__ Bf,
    void* __restrict__ Cv, float* __restrict__ rsum,
    int K, int lda, int ldb, int ldc,
    int mode, int ofp16, int bnn, int oexp, int oscale,
    long long sA, long long sB, long long sC)
{
    const int bz = blockIdx.z;
    Af += (size_t)bz * sA;
    Bf += (size_t)bz * sB;

    int row0, col0;
    if (mode == 1) {
        const int t = blockIdx.x;
        int r = (int)((__fsqrt_rn(8.f * (float)t + 1.f) - 1.f) * 0.5f);
        while ((r + 1) * (r + 2) / 2 <= t) r++;
        while (r * (r + 1) / 2 > t) r--;
        row0 = r * 128;
        col0 = (t - r * (r + 1) / 2) * 128;
    } else if (mode == 2) {
        const int by = (int)gridDim.y - 1 - (int)blockIdx.y;  // heavy first
        row0 = by * 128;
        col0 = blockIdx.x * 128;
    } else {
        row0 = blockIdx.y * 128;
        col0 = blockIdx.x * 128;
    }
    const int kend = (mode == 2) ? (row0 + 128) : K;
    const int nc = kend / KC;

    extern __shared__ char smc[];
    const uint32_t smb = smem_u32(smc);
    const int tid  = threadIdx.x;
    const int lane = tid & 31;
    const int wid  = tid >> 5;
    const int m0 = (wid & 1) * 64;
    const int n0 = (wid >> 1) * 32;

    float acc[4][4][4];
#pragma unroll
    for (int i = 0; i < 4; i++)
#pragma unroll
        for (int j = 0; j < 4; j++)
#pragma unroll
            for (int q = 0; q < 4; q++) acc[i][j][q] = 0.f;

    const int lch  = tid & 7;
    const int lr0  = tid >> 3;
    const int lch2 = tid & 15;
    const int lr2  = tid >> 4;

    auto do_load = [&](int st, int k0) {
        const uint32_t sb = smb + (uint32_t)st * STGB;
        const h16* pA = Af + (size_t)row0 * lda + k0;
#pragma unroll
        for (int j = 0; j < 4; j++) {
            const int row = lr0 + j * 32;
            CP_ASYNC16(sb + (uint32_t)(row * ROWB + lch * 16),
                       pA + (size_t)row * lda + lch * 8);
        }
        if (!bnn) {
            const h16* pB = Bf + (size_t)col0 * ldb + k0;
#pragma unroll
            for (int j = 0; j < 4; j++) {
                const int row = lr0 + j * 32;
                CP_ASYNC16(sb + MATB + (uint32_t)(row * ROWB + lch * 16),
                           pB + (size_t)row * ldb + lch * 8);
            }
        } else {
            const h16* pB = Bf + (size_t)k0 * ldb + col0;
#pragma unroll
            for (int j = 0; j < 4; j++) {
                const int row = lr2 + j * 16;
                CP_ASYNC16(sb + MATB + (uint32_t)(row * ROWBB + lch2 * 16),
                           pB + (size_t)row * ldb + lch2 * 8);
            }
        }
    };

    // PDL: all producer-data reads happen after this point.
    grid_dep_sync();

    do_load(0, 0);
    CP_COMMIT();
    do_load(1, KC);
    CP_COMMIT();

    for (int c = 0; c < nc; c++) {
        CP_WAIT1();
        __syncthreads();
        if (c + 2 < nc) do_load((c + 2) % NSTG, (c + 2) * KC);
        CP_COMMIT();

        const uint32_t base = smb + (uint32_t)(c % NSTG) * STGB;
#pragma unroll
        for (int kk = 0; kk < 4; kk++) {
            uint32_t a[4][4];
#pragma unroll
            for (int mi = 0; mi < 4; mi++) {
                const uint32_t ad = base +
                    (uint32_t)((m0 + mi * 16 + (lane & 15)) * ROWB +
                               (kk * 2 + (lane >> 4)) * 16);
                ldsm4(a[mi][0], a[mi][1], a[mi][2], a[mi][3], ad);
            }
            uint32_t bb[4][2];
            if (!bnn) {
#pragma unroll
                for (int np = 0; np < 2; np++) {
                    const int rb = n0 + np * 16 + (lane & 7) + ((lane >> 4) << 3);
                    const int ch = kk * 2 + ((lane >> 3) & 1);
                    const uint32_t ad = base + MATB +
                        (uint32_t)(rb * ROWB + ch * 16);
                    ldsm4(bb[np*2][0], bb[np*2][1],
                          bb[np*2+1][0], bb[np*2+1][1], ad);
                }
            } else {
#pragma unroll
                for (int g = 0; g < 2; g++) {
                    const uint32_t ad = base + MATB +
                        (uint32_t)((kk * 16 + (lane & 15)) * ROWBB +
                                   (n0 + g * 16 + ((lane >> 4) << 3)) * 2);
                    ldsm4t(bb[g*2][0], bb[g*2][1],
                           bb[g*2+1][0], bb[g*2+1][1], ad);
                }
            }
#pragma unroll
            for (int mi = 0; mi < 4; mi++)
#pragma unroll
                for (int ni = 0; ni < 4; ni++)
                    mma16816(acc[mi][ni], a[mi], bb[ni]);
        }
    }

    // ---------------- epilogues ----------------
    const int er = lane >> 2;
    const int ec = (lane & 3) * 2;

    if (oexp) {
        h16* C = (h16*)Cv + (size_t)bz * sC;
        float* rs = rsum + (size_t)bz * Tsz;
#pragma unroll
        for (int mi = 0; mi < 4; mi++) {
            const int rlo = row0 + m0 + mi * 16 + er;
            const int rhi = rlo + 8;
            float slo = 0.f, shi = 0.f;
#pragma unroll
            for (int ni = 0; ni < 4; ni++) {
                const int cc = col0 + n0 + ni * 8 + ec;
                float p0 = (cc     <= rlo) ? __expf(acc[mi][ni][0] * SMSCALE) : 0.f;
                float p1 = (cc + 1 <= rlo) ? __expf(acc[mi][ni][1] * SMSCALE) : 0.f;
                float p2 = (cc     <= rhi) ? __expf(acc[mi][ni][2] * SMSCALE) : 0.f;
                float p3 = (cc + 1 <= rhi) ? __expf(acc[mi][ni][3] * SMSCALE) : 0.f;
                __half2 h0 = __floats2half2_rn(p0, p1);
                __half2 h1 = __floats2half2_rn(p2, p3);
                *(__half2*)&C[(size_t)rlo * ldc + cc] = h0;
                *(__half2*)&C[(size_t)rhi * ldc + cc] = h1;
                slo += p0 + p1;
                shi += p2 + p3;
            }
            slo += __shfl_xor_sync(0xffffffffu, slo, 1);
            slo += __shfl_xor_sync(0xffffffffu, slo, 2);
            shi += __shfl_xor_sync(0xffffffffu, shi, 1);
            shi += __shfl_xor_sync(0xffffffffu, shi, 2);
            if ((lane & 3) == 0) {
                atomicAdd(&rs[rlo], slo);
                atomicAdd(&rs[rhi], shi);
            }
        }
    } else if (!ofp16) {
        float* C = (float*)Cv + (size_t)bz * sC;
        const float* rs = rsum + (size_t)bz * Tsz;
#pragma unroll
        for (int mi = 0; mi < 4; mi++) {
            const int r = row0 + m0 + mi * 16 + er;
            float ilo = 1.f, ihi = 1.f;
            if (oscale) {
                ilo = __fdividef(1.f, rs[r]);
                ihi = __fdividef(1.f, rs[r + 8]);
            }
#pragma unroll
            for (int ni = 0; ni < 4; ni++) {
                const int cc = col0 + n0 + ni * 8 + ec;
                *(float2*)&C[(size_t)r * ldc + cc] =
                    make_float2(acc[mi][ni][0] * ilo, acc[mi][ni][1] * ilo);
                *(float2*)&C[(size_t)(r + 8) * ldc + cc] =
                    make_float2(acc[mi][ni][2] * ihi, acc[mi][ni][3] * ihi);
            }
        }
    } else {
        h16* C = (h16*)Cv + (size_t)bz * sC;
#pragma unroll
        for (int mi = 0; mi < 4; mi++) {
            const int r = row0 + m0 + mi * 16 + er;
#pragma unroll
            for (int ni = 0; ni < 4; ni++) {
                const int cc = col0 + n0 + ni * 8 + ec;
                __half2 h0 = __floats2half2_rn(acc[mi][ni][0], acc[mi][ni][1]);
                __half2 h1 = __floats2half2_rn(acc[mi][ni][2], acc[mi][ni][3]);
                *(__half2*)&C[(size_t)r * ldc + cc] = h0;
                *(__half2*)&C[(size_t)(r + 8) * ldc + cc] = h1;
            }
        }
    }
}

// ---------------- fused prep: x fp16 + Wk fp16 + Wq^T + Wv^T ----------------
#define NXB (BT * Dsz / 1024)        // 8192 blocks for x
#define NWB (Dsz * Dsz / 1024)       // 1024 blocks per weight

__global__ void __launch_bounds__(256) prep(
    const float* __restrict__ x,  const float* __restrict__ Wq,
    const float* __restrict__ Wk, const float* __restrict__ Wv,
    h16* __restrict__ xf, h16* __restrict__ wqt,
    h16* __restrict__ wkf, h16* __restrict__ wvt /* ld 2*Dsz */)
{
    __shared__ float tile[32][33];
    const int bid = blockIdx.x;
    const int tid = threadIdx.x;

    if (bid < NXB + NWB) {
        const float* in = (bid < NXB) ? x : Wk;
        h16* o = (bid < NXB) ? xf : wkf;
        const int i = (bid < NXB ? bid : bid - NXB) * 256 + tid;
        float4 v = ((const float4*)in)[i];
        __half2 p0 = __floats2half2_rn(v.x, v.y);
        __half2 p1 = __floats2half2_rn(v.z, v.w);
        uint2 u;
        u.x = *(uint32_t*)&p0;
        u.y = *(uint32_t*)&p1;
        ((uint2*)o)[i] = u;
    } else {
        const int t = bid - (NXB + NWB);
        const bool isq = t < NWB;
        const int tt = isq ? t : t - NWB;
        const float* w = isq ? Wq : Wv;
        h16* o = isq ? wqt : wvt;
        const int ldo = isq ? Dsz : 2 * Dsz;
        const int d0 = (tt & 31) * 32;
        const int o0 = (tt >> 5) * 32;
        const int tx = tid & 31, ty = tid >> 5;
#pragma unroll
        for (int j = ty; j < 32; j += 8)
            tile[j][tx] = w[(size_t)(o0 + j) * Dsz + d0 + tx];
        __syncthreads();
#pragma unroll
        for (int j = ty; j < 32; j += 8)
            o[(size_t)(d0 + j) * ldo + o0 + tx] = __float2half_rn(tile[tx][j]);
    }
}

// ---------------- conv_m: sum 4 fp16 split-K partials -> B' cols [0,1024) ---
__global__ void __launch_bounds__(256) conv_m(
    const h16* __restrict__ mp, h16* __restrict__ bc)
{
    grid_dep_sync();
    const int i = blockIdx.x * 256 + threadIdx.x;   // uint4 units
    const int row = i >> 7;
    const int cb  = i & 127;
    const uint4* p = (const uint4*)mp;
    const int ps = (Dsz * Dsz) / 8;

    float2 f[4] = {{0,0},{0,0},{0,0},{0,0}};
#pragma unroll
    for (int k = 0; k < 4; k++) {
        uint4 u = p[(size_t)k * ps + i];
        const __half2* h = (const __half2*)&u;
#pragma unroll
        for (int j = 0; j < 4; j++) {
            float2 v = __half22float2(h[j]);
            f[j].x += v.x;
            f[j].y += v.y;
        }
    }
    uint4 o;
    __half2* oh = (__half2*)&o;
#pragma unroll
    for (int j = 0; j < 4; j++)
        oh[j] = __floats2half2_rn(f[j].x, f[j].y);
    ((uint4*)bc)[(size_t)row * 256 + cb] = o;
}

// ---------------- launch ------------------------------------------------------
extern "C" void kernel_launch(void* const* d_in, const int* in_sizes, int n_in,
                              void* d_out, int out_size)
{
    (void)in_sizes; (void)n_in; (void)out_size;
    const float* x  = (const float*)d_in[0];
    const float* Wq = (const float*)d_in[1];
    const float* Wk = (const float*)d_in[2];
    const float* Wv = (const float*)d_in[3];
    float* out = (float*)d_out;

    h16 *xf, *wqt, *wk, *mp, *bc, *av, *pf;
    float* rsum;
    cudaGetSymbolAddress((void**)&xf,   g_xf);
    cudaGetSymbolAddress((void**)&wqt,  g_wqt);
    cudaGetSymbolAddress((void**)&wk,   g_wk);
    cudaGetSymbolAddress((void**)&mp,   g_mp);
    cudaGetSymbolAddress((void**)&bc,   g_bc);
    cudaGetSymbolAddress((void**)&av,   g_av);
    cudaGetSymbolAddress((void**)&pf,   g_pf);
    cudaGetSymbolAddress((void**)&rsum, g_rsum);

    cudaFuncSetAttribute(hgemm, cudaFuncAttributeMaxDynamicSharedMemorySize,
                         SMEMB);

    // PDL launch config (programmatic stream serialization)
    cudaLaunchAttribute at[1];
    at[0].id = cudaLaunchAttributeProgrammaticStreamSerialization;
    at[0].val.programmaticStreamSerializationAllowed = 1;
    cudaLaunchConfig_t cfg = {};
    cfg.blockDim = {256, 1, 1};
    cfg.dynamicSmemBytes = SMEMB;
    cfg.stream = 0;
    cfg.attrs = at;
    cfg.numAttrs = 1;

    // zero softmax row sums
    cudaMemsetAsync(rsum, 0, (size_t)Bsz * Tsz * sizeof(float));

    // fused conversions (no producer; plain launch)
    prep<<<NXB + 3 * NWB, 256>>>(x, Wq, Wk, Wv, xf, wqt, wk, bc + Dsz);

    // M = Wq^T @ Wk, split-K=4 -> 4 fp16 partials   [PDL after prep]
    cfg.gridDim = {Dsz / 128, Dsz / 128, 4};
    cudaLaunchKernelEx(&cfg, hgemm,
        (const h16*)wqt, (const h16*)wk, (void*)mp, rsum,
        256, (int)Dsz, (int)Dsz, (int)Dsz, 0, 1, 1, 0, 0,
        (long long)256, (long long)256 * Dsz, (long long)Dsz * Dsz);

    // reduce partials -> B' cols [0,1024)           [PDL after M]
    {
        cudaLaunchConfig_t c2 = {};
        c2.gridDim = {(Dsz * Dsz / 8) / 256, 1, 1};
        c2.blockDim = {256, 1, 1};
        c2.stream = 0;
        c2.attrs = at;
        c2.numAttrs = 1;
        cudaLaunchKernelEx(&c2, conv_m, (const h16*)mp, (h16*)bc);
    }

    // [A | V] = x @ B'                              [PDL after conv_m]
    cfg.gridDim = {2 * Dsz / 128, BT / 128, 1};
    cudaLaunchKernelEx(&cfg, hgemm,
        (const h16*)xf, (const h16*)bc, (void*)av, rsum,
        (int)Dsz, (int)Dsz, (int)(2 * Dsz), (int)(2 * Dsz), 0, 1, 1, 0, 0,
        (long long)0, (long long)0, (long long)0);

    const h16* am = av;             // A, row stride 2048
    const h16* vp = av + Dsz;       // V, row stride 2048

    // P_unnorm = exp(scale * A @ x^T)               [PDL after AV]
    const unsigned ntiles = (Tsz / 128) * (Tsz / 128 + 1) / 2;   // 136
    cfg.gridDim = {ntiles, 1, Bsz};
    cudaLaunchKernelEx(&cfg, hgemm,
        am, (const h16*)xf, (void*)pf, rsum,
        (int)Dsz, (int)(2 * Dsz), (int)Dsz, (int)Tsz, 1, 0, 0, 1, 0,
        (long long)Tsz * 2 * Dsz, (long long)Tsz * Dsz,
        (long long)Tsz * Tsz);

    // O = (P @ V) * (1/rowsum)                      [PDL after S]
    cfg.gridDim = {Dsz / 128, Tsz / 128, Bsz};
    cudaLaunchKernelEx(&cfg, hgemm,
        (const h16*)pf, vp, (void*)out, rsum,
        (int)Tsz, (int)Tsz, (int)(2 * Dsz), (int)Dsz, 2, 0, 1, 0, 1,
        (long long)Tsz * Tsz, (long long)Tsz * 2 * Dsz,
        (long long)Tsz * Dsz);
}

// round 15
// speedup vs baseline: 1.0286x; 1.0011x over previous
#include <cuda_runtime.h>
#include <cuda_fp16.h>
#include <stdint.h>
#include <math.h>

#define Bsz 4
#define Tsz 2048
#define Dsz 1024
#define BT  (Bsz * Tsz)

typedef __half h16;

// ---------------- scratch (__device__ globals; allocation-free rule) -------
__device__ __align__(16) h16 g_xf[(size_t)BT * Dsz];
__device__ __align__(16) h16 g_wqt[(size_t)Dsz * Dsz];       // Wq^T fp16
__device__ __align__(16) h16 g_wk[(size_t)Dsz * Dsz];        // Wk fp16
__device__ __align__(16) h16 g_mp[4][(size_t)Dsz * Dsz];     // M split-K partials
__device__ __align__(16) h16 g_bc[(size_t)Dsz * 2 * Dsz];    // B' = [M | Wv^T]
__device__ __align__(16) h16 g_av[(size_t)BT * 2 * Dsz];     // [A | V]
__device__ __align__(16) h16 g_pf[(size_t)Bsz * Tsz * Tsz];  // P (unnormalized)
__device__ __align__(16) float g_rsum[(size_t)Bsz * Tsz];    // softmax row sums

// ---------------- low-level helpers (plain sm_80-era PTX only) --------------
__device__ __forceinline__ uint32_t smem_u32(const void* p) {
    uint32_t a;
    asm("{ .reg .u64 t; cvta.to.shared.u64 t, %1; cvt.u32.u64 %0, t; }"
        : "=r"(a) : "l"(p));
    return a;
}

#define CP_ASYNC16(dst, src) \
    asm volatile("cp.async.cg.shared.global [%0], [%1], 16;" \
                 :: "r"(dst), "l"(src))
#define CP_COMMIT() asm volatile("cp.async.commit_group;")
#define CP_WAIT1()  asm volatile("cp.async.wait_group 1;")

__device__ __forceinline__ void ldsm4(uint32_t& r0, uint32_t& r1,
                                      uint32_t& r2, uint32_t& r3,
                                      uint32_t addr) {
    asm volatile("ldmatrix.sync.aligned.m8n8.x4.shared.b16 {%0,%1,%2,%3}, [%4];"
                 : "=r"(r0), "=r"(r1), "=r"(r2), "=r"(r3) : "r"(addr));
}

__device__ __forceinline__ void ldsm4t(uint32_t& r0, uint32_t& r1,
                                       uint32_t& r2, uint32_t& r3,
                                       uint32_t addr) {
    asm volatile(
        "ldmatrix.sync.aligned.m8n8.x4.trans.shared.b16 {%0,%1,%2,%3}, [%4];"
        : "=r"(r0), "=r"(r1), "=r"(r2), "=r"(r3) : "r"(addr));
}

__device__ __forceinline__ void mma16816(float* d, const uint32_t* a,
                                         const uint32_t* b) {
    asm volatile(
        "mma.sync.aligned.m16n8k16.row.col.f32.f16.f16.f32 "
        "{%0,%1,%2,%3}, {%4,%5,%6,%7}, {%8,%9}, {%0,%1,%2,%3};"
        : "+f"(d[0]), "+f"(d[1]), "+f"(d[2]), "+f"(d[3])
        : "r"(a[0]), "r"(a[1]), "r"(a[2]), "r"(a[3]), "r"(b[0]), "r"(b[1]));
}

// PDL: wait for the predecessor kernel's memory to be visible.
__device__ __forceinline__ void grid_dep_sync() {
    asm volatile("griddepcontrol.wait;" ::: "memory");
}

// ---------------- HMMA GEMM (proven at-ceiling config) -----------------------
// C[M,N] = A[M,K] * op(B).  bnn=0: B is [N,K] (NT).  bnn=1: B is [K,N] (NN).
// mode 0: full grid.  mode 1: triangular tile index.  mode 2: kend=row0+128.
// ofp16: fp16 C.  oexp: exp epilogue (fp16 P + atomic row sums, causal mask).
// oscale: fp32 C scaled by 1/rsum[row].
#define KC     64
#define ROWB   144
#define ROWBB  272
#define MATB   (128 * ROWB)
#define STGB   (2 * MATB)
#define NSTG   3
#define SMEMB  (NSTG * STGB)     // 110592 B
#define SMSCALE 0.03125f         // 1/sqrt(1024)

__global__ void __launch_bounds__(256, 2) hgemm(
    const h16* __restrict__ Af, const h16* __restrict__ Bf,
    void* __restrict__ Cv, float* __restrict__ rsum,
    int K, int lda, int ldb, int ldc,
    int mode, int ofp16, int bnn, int oexp, int oscale,
    long long sA, long long sB, long long sC)
{
    const int bz = blockIdx.z;
    Af += (size_t)bz * sA;
    Bf += (size_t)bz * sB;

    int row0, col0;
    if (mode == 1) {
        const int t = blockIdx.x;
        int r = (int)((__fsqrt_rn(8.f * (float)t + 1.f) - 1.f) * 0.5f);
        while ((r + 1) * (r + 2) / 2 <= t) r++;
        while (r * (r + 1) / 2 > t) r--;
        row0 = r * 128;
        col0 = (t - r * (r + 1) / 2) * 128;
    } else if (mode == 2) {
        const int by = (int)gridDim.y - 1 - (int)blockIdx.y;  // heavy first
        row0 = by * 128;
        col0 = blockIdx.x * 128;
    } else {
        row0 = blockIdx.y * 128;
        col0 = blockIdx.x * 128;
    }
    const int kend = (mode == 2) ? (row0 + 128) : K;
    const int nc = kend / KC;

    extern __shared__ char smc[];
    const uint32_t smb = smem_u32(smc);
    const int tid  = threadIdx.x;
    const int lane = tid & 31;
    const int wid  = tid >> 5;
    const int m0 = (wid & 1) * 64;
    const int n0 = (wid >> 1) * 32;

    float acc[4][4][4];
#pragma unroll
    for (int i = 0; i < 4; i++)
#pragma unroll
        for (int j = 0; j < 4; j++)
#pragma unroll
            for (int q = 0; q < 4; q++) acc[i][j][q] = 0.f;

    const int lch  = tid & 7;
    const int lr0  = tid >> 3;
    const int lch2 = tid & 15;
    const int lr2  = tid >> 4;

    auto do_load = [&](int st, int k0) {
        const uint32_t sb = smb + (uint32_t)st * STGB;
        const h16* pA = Af + (size_t)row0 * lda + k0;
#pragma unroll
        for (int j = 0; j < 4; j++) {
            const int row = lr0 + j * 32;
            CP_ASYNC16(sb + (uint32_t)(row * ROWB + lch * 16),
                       pA + (size_t)row * lda + lch * 8);
        }
        if (!bnn) {
            const h16* pB = Bf + (size_t)col0 * ldb + k0;
#pragma unroll
            for (int j = 0; j < 4; j++) {
                const int row = lr0 + j * 32;
                CP_ASYNC16(sb + MATB + (uint32_t)(row * ROWB + lch * 16),
                           pB + (size_t)row * ldb + lch * 8);
            }
        } else {
            const h16* pB = Bf + (size_t)k0 * ldb + col0;
#pragma unroll
            for (int j = 0; j < 4; j++) {
                const int row = lr2 + j * 16;
                CP_ASYNC16(sb + MATB + (uint32_t)(row * ROWBB + lch2 * 16),
                           pB + (size_t)row * ldb + lch2 * 8);
            }
        }
    };

    // PDL: all producer-data reads happen after this point.
    grid_dep_sync();

    do_load(0, 0);
    CP_COMMIT();
    do_load(1, KC);
    CP_COMMIT();

    for (int c = 0; c < nc; c++) {
        CP_WAIT1();
        __syncthreads();
        if (c + 2 < nc) do_load((c + 2) % NSTG, (c + 2) * KC);
        CP_COMMIT();

        const uint32_t base = smb + (uint32_t)(c % NSTG) * STGB;
#pragma unroll
        for (int kk = 0; kk < 4; kk++) {
            uint32_t a[4][4];
#pragma unroll
            for (int mi = 0; mi < 4; mi++) {
                const uint32_t ad = base +
                    (uint32_t)((m0 + mi * 16 + (lane & 15)) * ROWB +
                               (kk * 2 + (lane >> 4)) * 16);
                ldsm4(a[mi][0], a[mi][1], a[mi][2], a[mi][3], ad);
            }
            uint32_t bb[4][2];
            if (!bnn) {
#pragma unroll
                for (int np = 0; np < 2; np++) {
                    const int rb = n0 + np * 16 + (lane & 7) + ((lane >> 4) << 3);
                    const int ch = kk * 2 + ((lane >> 3) & 1);
                    const uint32_t ad = base + MATB +
                        (uint32_t)(rb * ROWB + ch * 16);
                    ldsm4(bb[np*2][0], bb[np*2][1],
                          bb[np*2+1][0], bb[np*2+1][1], ad);
                }
            } else {
#pragma unroll
                for (int g = 0; g < 2; g++) {
                    const uint32_t ad = base + MATB +
                        (uint32_t)((kk * 16 + (lane & 15)) * ROWBB +
                                   (n0 + g * 16 + ((lane >> 4) << 3)) * 2);
                    ldsm4t(bb[g*2][0], bb[g*2][1],
                           bb[g*2+1][0], bb[g*2+1][1], ad);
                }
            }
#pragma unroll
            for (int mi = 0; mi < 4; mi++)
#pragma unroll
                for (int ni = 0; ni < 4; ni++)
                    mma16816(acc[mi][ni], a[mi], bb[ni]);
        }
    }

    // ---------------- epilogues ----------------
    const int er = lane >> 2;
    const int ec = (lane & 3) * 2;

    if (oexp) {
        h16* C = (h16*)Cv + (size_t)bz * sC;
        float* rs = rsum + (size_t)bz * Tsz;
#pragma unroll
        for (int mi = 0; mi < 4; mi++) {
            const int rlo = row0 + m0 + mi * 16 + er;
            const int rhi = rlo + 8;
            float slo = 0.f, shi = 0.f;
#pragma unroll
            for (int ni = 0; ni < 4; ni++) {
                const int cc = col0 + n0 + ni * 8 + ec;
                float p0 = (cc     <= rlo) ? __expf(acc[mi][ni][0] * SMSCALE) : 0.f;
                float p1 = (cc + 1 <= rlo) ? __expf(acc[mi][ni][1] * SMSCALE) : 0.f;
                float p2 = (cc     <= rhi) ? __expf(acc[mi][ni][2] * SMSCALE) : 0.f;
                float p3 = (cc + 1 <= rhi) ? __expf(acc[mi][ni][3] * SMSCALE) : 0.f;
                __half2 h0 = __floats2half2_rn(p0, p1);
                __half2 h1 = __floats2half2_rn(p2, p3);
                *(__half2*)&C[(size_t)rlo * ldc + cc] = h0;
                *(__half2*)&C[(size_t)rhi * ldc + cc] = h1;
                slo += p0 + p1;
                shi += p2 + p3;
            }
            slo += __shfl_xor_sync(0xffffffffu, slo, 1);
            slo += __shfl_xor_sync(0xffffffffu, slo, 2);
            shi += __shfl_xor_sync(0xffffffffu, shi, 1);
            shi += __shfl_xor_sync(0xffffffffu, shi, 2);
            if ((lane & 3) == 0) {
                atomicAdd(&rs[rlo], slo);
                atomicAdd(&rs[rhi], shi);
            }
        }
    } else if (!ofp16) {
        float* C = (float*)Cv + (size_t)bz * sC;
        const float* rs = rsum + (size_t)bz * Tsz;
#pragma unroll
        for (int mi = 0; mi < 4; mi++) {
            const int r = row0 + m0 + mi * 16 + er;
            float ilo = 1.f, ihi = 1.f;
            if (oscale) {
                ilo = __fdividef(1.f, rs[r]);
                ihi = __fdividef(1.f, rs[r + 8]);
            }
#pragma unroll
            for (int ni = 0; ni < 4; ni++) {
                const int cc = col0 + n0 + ni * 8 + ec;
                *(float2*)&C[(size_t)r * ldc + cc] =
                    make_float2(acc[mi][ni][0] * ilo, acc[mi][ni][1] * ilo);
                *(float2*)&C[(size_t)(r + 8) * ldc + cc] =
                    make_float2(acc[mi][ni][2] * ihi, acc[mi][ni][3] * ihi);
            }
        }
    } else {
        h16* C = (h16*)Cv + (size_t)bz * sC;
#pragma unroll
        for (int mi = 0; mi < 4; mi++) {
            const int r = row0 + m0 + mi * 16 + er;
#pragma unroll
            for (int ni = 0; ni < 4; ni++) {
                const int cc = col0 + n0 + ni * 8 + ec;
                __half2 h0 = __floats2half2_rn(acc[mi][ni][0], acc[mi][ni][1]);
                __half2 h1 = __floats2half2_rn(acc[mi][ni][2], acc[mi][ni][3]);
                *(__half2*)&C[(size_t)r * ldc + cc] = h0;
                *(__half2*)&C[(size_t)(r + 8) * ldc + cc] = h1;
            }
        }
    }
}

// ---------------- prep kernels (split so V can start early) -----------------
#define NXB (BT * Dsz / 1024)        // 8192 blocks for x
#define NWB (Dsz * Dsz / 1024)       // 1024 blocks per weight

__global__ void __launch_bounds__(256) prep_x(
    const float* __restrict__ x, h16* __restrict__ xf)
{
    const int i = blockIdx.x * 256 + threadIdx.x;
    float4 v = ((const float4*)x)[i];
    __half2 p0 = __floats2half2_rn(v.x, v.y);
    __half2 p1 = __floats2half2_rn(v.z, v.w);
    uint2 u;
    u.x = *(uint32_t*)&p0;
    u.y = *(uint32_t*)&p1;
    ((uint2*)xf)[i] = u;
}

__global__ void __launch_bounds__(256) prep_w(
    const float* __restrict__ Wq, const float* __restrict__ Wk,
    const float* __restrict__ Wv,
    h16* __restrict__ wqt, h16* __restrict__ wkf,
    h16* __restrict__ wvt /* ld 2*Dsz */)
{
    __shared__ float tile[32][33];
    const int bid = blockIdx.x;
    const int tid = threadIdx.x;

    if (bid < NWB) {
        const int i = bid * 256 + tid;
        float4 v = ((const float4*)Wk)[i];
        __half2 p0 = __floats2half2_rn(v.x, v.y);
        __half2 p1 = __floats2half2_rn(v.z, v.w);
        uint2 u;
        u.x = *(uint32_t*)&p0;
        u.y = *(uint32_t*)&p1;
        ((uint2*)wkf)[i] = u;
    } else {
        const int t = bid - NWB;
        const bool isq = t < NWB;
        const int tt = isq ? t : t - NWB;
        const float* w = isq ? Wq : Wv;
        h16* o = isq ? wqt : wvt;
        const int ldo = isq ? Dsz : 2 * Dsz;
        const int d0 = (tt & 31) * 32;
        const int o0 = (tt >> 5) * 32;
        const int tx = tid & 31, ty = tid >> 5;
#pragma unroll
        for (int j = ty; j < 32; j += 8)
            tile[j][tx] = w[(size_t)(o0 + j) * Dsz + d0 + tx];
        __syncthreads();
#pragma unroll
        for (int j = ty; j < 32; j += 8)
            o[(size_t)(d0 + j) * ldo + o0 + tx] = __float2half_rn(tile[tx][j]);
    }
}

// ---------------- conv_m: sum 4 fp16 split-K partials -> B' cols [0,1024) ---
__global__ void __launch_bounds__(256) conv_m(
    const h16* __restrict__ mp, h16* __restrict__ bc)
{
    grid_dep_sync();
    const int i = blockIdx.x * 256 + threadIdx.x;   // uint4 units
    const int row = i >> 7;
    const int cb  = i & 127;
    const uint4* p = (const uint4*)mp;
    const int ps = (Dsz * Dsz) / 8;

    float2 f[4] = {{0,0},{0,0},{0,0},{0,0}};
#pragma unroll
    for (int k = 0; k < 4; k++) {
        uint4 u = p[(size_t)k * ps + i];
        const __half2* h = (const __half2*)&u;
#pragma unroll
        for (int j = 0; j < 4; j++) {
            float2 v = __half22float2(h[j]);
            f[j].x += v.x;
            f[j].y += v.y;
        }
    }
    uint4 o;
    __half2* oh = (__half2*)&o;
#pragma unroll
    for (int j = 0; j < 4; j++)
        oh[j] = __floats2half2_rn(f[j].x, f[j].y);
    ((uint4*)bc)[(size_t)row * 256 + cb] = o;
}

// ---------------- launch ------------------------------------------------------
extern "C" void kernel_launch(void* const* d_in, const int* in_sizes, int n_in,
                              void* d_out, int out_size)
{
    (void)in_sizes; (void)n_in; (void)out_size;
    const float* x  = (const float*)d_in[0];
    const float* Wq = (const float*)d_in[1];
    const float* Wk = (const float*)d_in[2];
    const float* Wv = (const float*)d_in[3];
    float* out = (float*)d_out;

    h16 *xf, *wqt, *wk, *mp, *bc, *av, *pf;
    float* rsum;
    cudaGetSymbolAddress((void**)&xf,   g_xf);
    cudaGetSymbolAddress((void**)&wqt,  g_wqt);
    cudaGetSymbolAddress((void**)&wk,   g_wk);
    cudaGetSymbolAddress((void**)&mp,   g_mp);
    cudaGetSymbolAddress((void**)&bc,   g_bc);
    cudaGetSymbolAddress((void**)&av,   g_av);
    cudaGetSymbolAddress((void**)&pf,   g_pf);
    cudaGetSymbolAddress((void**)&rsum, g_rsum);

    cudaFuncSetAttribute(hgemm, cudaFuncAttributeMaxDynamicSharedMemorySize,
                         SMEMB);

    // lazily created side stream + events (host objects only)
    static cudaStream_t s2 = nullptr;
    static cudaEvent_t e0 = nullptr, e_x = nullptr, e_w = nullptr,
                       e_v = nullptr;
    if (!s2) {
        cudaStreamCreateWithFlags(&s2, cudaStreamNonBlocking);
        cudaEventCreateWithFlags(&e0,  cudaEventDisableTiming);
        cudaEventCreateWithFlags(&e_x, cudaEventDisableTiming);
        cudaEventCreateWithFlags(&e_w, cudaEventDisableTiming);
        cudaEventCreateWithFlags(&e_v, cudaEventDisableTiming);
    }

    // PDL launch config (programmatic stream serialization)
    cudaLaunchAttribute at[1];
    at[0].id = cudaLaunchAttributeProgrammaticStreamSerialization;
    at[0].val.programmaticStreamSerializationAllowed = 1;
    cudaLaunchConfig_t cfg = {};
    cfg.blockDim = {256, 1, 1};
    cfg.dynamicSmemBytes = SMEMB;
    cfg.stream = 0;
    cfg.attrs = at;
    cfg.numAttrs = 1;

    // fork s2 off the capture-origin stream
    cudaEventRecord(e0, 0);
    cudaStreamWaitEvent(s2, e0, 0);

    // s2: zero rsum, convert x
    cudaMemsetAsync(rsum, 0, (size_t)Bsz * Tsz * sizeof(float), s2);
    prep_x<<<NXB, 256, 0, s2>>>(x, xf);
    cudaEventRecord(e_x, s2);

    // s0: weight prep (Wk convert, Wq^T, Wv^T into B' cols [1024,2048))
    prep_w<<<3 * NWB, 256>>>(Wq, Wk, Wv, wqt, wk, bc + Dsz);
    cudaEventRecord(e_w, 0);

    // s2: V = x @ Wv^T — overlaps the half-idle M-chain on s0
    cudaStreamWaitEvent(s2, e_w, 0);
    {
        cudaLaunchConfig_t cv = cfg;
        cv.stream = s2;
        cv.gridDim = {Dsz / 128, BT / 128, 1};
        cudaLaunchKernelEx(&cv, hgemm,
            (const h16*)xf, (const h16*)(bc + Dsz), (void*)(av + Dsz), rsum,
            (int)Dsz, (int)Dsz, (int)(2 * Dsz), (int)(2 * Dsz), 0, 1, 1, 0, 0,
            (long long)0, (long long)0, (long long)0);
    }
    cudaEventRecord(e_v, s2);

    // s0: M = Wq^T @ Wk, split-K=4 -> partials       [PDL after prep_w]
    cfg.gridDim = {Dsz / 128, Dsz / 128, 4};
    cudaLaunchKernelEx(&cfg, hgemm,
        (const h16*)wqt, (const h16*)wk, (void*)mp, rsum,
        256, (int)Dsz, (int)Dsz, (int)Dsz, 0, 1, 1, 0, 0,
        (long long)256, (long long)256 * Dsz, (long long)Dsz * Dsz);

    // s0: reduce partials -> B' cols [0,1024)        [PDL after M]
    {
        cudaLaunchConfig_t c2 = {};
        c2.gridDim = {(Dsz * Dsz / 8) / 256, 1, 1};
        c2.blockDim = {256, 1, 1};
        c2.stream = 0;
        c2.attrs = at;
        c2.numAttrs = 1;
        cudaLaunchKernelEx(&c2, conv_m, (const h16*)mp, (h16*)bc);
    }

    // s0: A = x @ M                                  [PDL after conv_m, + e_x]
    cudaStreamWaitEvent(0, e_x, 0);
    cfg.gridDim = {Dsz / 128, BT / 128, 1};
    cudaLaunchKernelEx(&cfg, hgemm,
        (const h16*)xf, (const h16*)bc, (void*)av, rsum,
        (int)Dsz, (int)Dsz, (int)(2 * Dsz), (int)(2 * Dsz), 0, 1, 1, 0, 0,
        (long long)0, (long long)0, (long long)0);

    const h16* am = av;             // A, row stride 2048
    const h16* vp = av + Dsz;       // V, row stride 2048

    // s0: P_unnorm = exp(scale * A @ x^T)            [PDL after A]
    const unsigned ntiles = (Tsz / 128) * (Tsz / 128 + 1) / 2;   // 136
    cfg.gridDim = {ntiles, 1, Bsz};
    cudaLaunchKernelEx(&cfg, hgemm,
        am, (const h16*)xf, (void*)pf, rsum,
        (int)Dsz, (int)(2 * Dsz), (int)Dsz, (int)Tsz, 1, 0, 0, 1, 0,
        (long long)Tsz * 2 * Dsz, (long long)Tsz * Dsz,
        (long long)Tsz * Tsz);

    // join V, then s0: O = (P @ V) * (1/rowsum)      [PDL after S, + e_v]
    cudaStreamWaitEvent(0, e_v, 0);
    cfg.gridDim = {Dsz / 128, Tsz / 128, Bsz};
    cudaLaunchKernelEx(&cfg, hgemm,
        (const h16*)pf, vp, (void*)out, rsum,
        (int)Tsz, (int)Tsz, (int)(2 * Dsz), (int)Dsz, 2, 0, 1, 0, 1,
        (long long)Tsz * Tsz, (long long)Tsz * 2 * Dsz,
        (long long)Tsz * Dsz);
}